// round 16
// baseline (speedup 1.0000x reference)
#include <cuda_runtime.h>
#include <cuda_fp16.h>
#include <stdint.h>

#define N_NODES 50000
#define N_EDGES 800000
#define D 64
#define LN_EPS 1e-5f
#define CAP 64                                    // deg mean 16, sigma 4; 64 = 12 sigma
#define ROWS_PER_BLK 128                          // 8 warps x 16 rows
#define GEMM_BLOCKS ((N_NODES + ROWS_PER_BLK - 1) / ROWS_PER_BLK)  // 391
#define INTERLEAVE 9                              // 1 gemm : 8 bin blocks
#define TOTAL_BLOCKS (GEMM_BLOCKS * INTERLEAVE)   // 3519
#define XH_STRIDE 72                              // halves; 144B rows, conflict-free

// Scratch (static device globals; zero-initialized at module load)
__device__ float4  g_xw4[N_NODES * (D / 4)];      // x @ W (fp32, self-loop path)
__device__ __half2 g_yh[N_NODES * (D / 2)];       // y = dinv * xw (fp16 gather table)
__device__ int   g_degi[N_NODES];                 // bin fill counters; zero between calls
__device__ int   g_cnt[N_NODES];                  // per-node edge count snapshot
__device__ float g_dinv[N_NODES];                 // rsqrt(1 + deg)
__device__ int   g_bin[N_NODES * CAP];            // src indices, bucketed by dst

__device__ __forceinline__ uint32_t smem_u32(const void* p) {
    return (uint32_t)__cvta_generic_to_shared(p);
}

// ---------------------------------------------------------------------------
// K1: fused  (a) xw = x @ W via HMMA (mma.sync m16n8k16, fp16 in, fp32 acc)
//            (b) edge binning, 1 edge/thread for max atomic parallelism.
// blockIdx % 9 == 0 -> gemm (391 blocks); else bin (3128 slots, 256 edges each).
// ---------------------------------------------------------------------------
__global__ void fused_gemm_bin_kernel(const float* __restrict__ x,
                                      const float* __restrict__ W,
                                      const int* __restrict__ src,
                                      const int* __restrict__ dst) {
    int tid = threadIdx.x;          // 256 threads flat
    if (blockIdx.x % INTERLEAVE != 0) {
        // -------- edge binning: 1 edge/thread --------
        int binBlk = blockIdx.x - blockIdx.x / INTERLEAVE - 1;   // 0..3127
        int e = binBlk * 256 + tid;
        if (e < N_EDGES) {
            int s = __ldg(src + e);
            int d = __ldg(dst + e);
            int r = atomicAdd(&g_degi[d], 1);
            if (r < CAP) g_bin[d * CAP + r] = s;
        }
        return;
    }
    // -------- gemm: 128 rows/block, warp = 16 rows x 64 cols --------
    __shared__ __align__(16) __half Wh[D * XH_STRIDE];            // 9.2 KB  [k][n]
    __shared__ __align__(16) __half Xh[ROWS_PER_BLK * XH_STRIDE]; // 18.4 KB [r][k]

    int row0 = (blockIdx.x / INTERLEAVE) * ROWS_PER_BLK;

    // stage W -> fp16 [k][n]
    {
        const float2* W2 = reinterpret_cast<const float2*>(W);
        for (int i = tid; i < D * (D / 2); i += 256) {
            int k = i >> 5, n2 = i & 31;
            float2 v = W2[i];
            *reinterpret_cast<__half2*>(&Wh[k * XH_STRIDE + n2 * 2]) =
                __floats2half2_rn(v.x, v.y);
        }
    }
    // stage x rows -> fp16 [r][k]
    {
        const float2* x2 = reinterpret_cast<const float2*>(x);
        for (int i = tid; i < ROWS_PER_BLK * (D / 2); i += 256) {
            int r = i >> 5, c2 = i & 31;
            int row = row0 + r;
            float2 v = (row < N_NODES) ? x2[(size_t)row * 32 + c2]
                                       : make_float2(0.f, 0.f);
            *reinterpret_cast<__half2*>(&Xh[r * XH_STRIDE + c2 * 2]) =
                __floats2half2_rn(v.x, v.y);
        }
    }
    __syncthreads();

    int warp = tid >> 5;
    int lane = tid & 31;
    int rw = warp * 16;                       // warp's first row within block

    float d0[8], d1[8], d2[8], d3[8];
#pragma unroll
    for (int nt = 0; nt < 8; nt++) { d0[nt] = d1[nt] = d2[nt] = d3[nt] = 0.f; }

    uint32_t a_base = smem_u32(Xh) +
        (uint32_t)(((rw + (lane & 15)) * XH_STRIDE + ((lane >> 4) << 3)) * 2);
    uint32_t b_base = smem_u32(Wh) + (uint32_t)(((lane & 15) * XH_STRIDE) * 2);

#pragma unroll
    for (int kc = 0; kc < 4; kc++) {          // k chunks of 16
        uint32_t a0, a1, a2, a3;
        asm volatile("ldmatrix.sync.aligned.m8n8.x4.shared.b16 {%0,%1,%2,%3}, [%4];"
                     : "=r"(a0), "=r"(a1), "=r"(a2), "=r"(a3)
                     : "r"(a_base + kc * 32));
#pragma unroll
        for (int nt = 0; nt < 8; nt++) {
            uint32_t b0, b1;
            asm volatile("ldmatrix.sync.aligned.m8n8.x2.trans.shared.b16 {%0,%1}, [%2];"
                         : "=r"(b0), "=r"(b1)
                         : "r"(b_base + (uint32_t)(kc * 16 * XH_STRIDE + nt * 8) * 2));
            asm volatile(
                "mma.sync.aligned.m16n8k16.row.col.f32.f16.f16.f32 "
                "{%0,%1,%2,%3}, {%4,%5,%6,%7}, {%8,%9}, {%0,%1,%2,%3};"
                : "+f"(d0[nt]), "+f"(d1[nt]), "+f"(d2[nt]), "+f"(d3[nt])
                : "r"(a0), "r"(a1), "r"(a2), "r"(a3), "r"(b0), "r"(b1));
        }
    }

    // write xw: lane g=l>>2 -> rows rw+g, rw+g+8; tg=l&3 -> col pair
    {
        int g = lane >> 2, tg = lane & 3;
        int rowA = row0 + rw + g;
        int rowB = rowA + 8;
        float2* xw2 = reinterpret_cast<float2*>(g_xw4);
#pragma unroll
        for (int nt = 0; nt < 8; nt++) {
            int cpair = nt * 4 + tg;
            if (rowA < N_NODES) xw2[(size_t)rowA * 32 + cpair] = make_float2(d0[nt], d1[nt]);
            if (rowB < N_NODES) xw2[(size_t)rowB * 32 + cpair] = make_float2(d2[nt], d3[nt]);
        }
    }
}

// ---------------------------------------------------------------------------
// K2: per node (warp per row): dinv = rsqrt(1+deg); y = half(dinv * xw);
// snapshot cnt; re-zero degi.
// ---------------------------------------------------------------------------
__global__ void prep_scale_kernel() {
    int warp = threadIdx.x >> 5;
    int lane = threadIdx.x & 31;
    int row = blockIdx.x * (blockDim.x >> 5) + warp;
    if (row >= N_NODES) return;

    int d = g_degi[row];
    float di = rsqrtf(1.0f + (float)d);
    if (lane == 0) {
        g_dinv[row] = di;
        g_cnt[row] = (d < CAP) ? d : CAP;
        g_degi[row] = 0;
    }
    const float2* xw2 = reinterpret_cast<const float2*>(g_xw4);
    float2 v = xw2[(size_t)row * 32 + lane];
    g_yh[(size_t)row * 32 + lane] = __floats2half2_rn(v.x * di, v.y * di);
}

// ---------------------------------------------------------------------------
// K3: fused gather (fp16 y table) + finalize. Warp per node.
// h = x + dinv_d * sum_s y_s + dinv_d^2 * xw_d + b ; LayerNorm; ReLU.
// ---------------------------------------------------------------------------
__global__ void gather_finalize_kernel(const float* __restrict__ x,
                                       const float* __restrict__ b,
                                       const float* __restrict__ gamma,
                                       const float* __restrict__ beta,
                                       float* __restrict__ out) {
    int warp = threadIdx.x >> 5;
    int lane = threadIdx.x & 31;
    int row = blockIdx.x * (blockDim.x >> 5) + warp;
    if (row >= N_NODES) return;

    int deg = g_cnt[row];
    const int* bin = g_bin + (size_t)row * CAP;

    float z0 = 0.f, z1 = 0.f;
#pragma unroll 4
    for (int k = 0; k < deg; k++) {
        int s = __ldg(bin + k);                      // warp-broadcast 4B
        float2 v = __half22float2(g_yh[(size_t)s * 32 + lane]);  // 128B/warp gather
        z0 += v.x;
        z1 += v.y;
    }

    float dr = g_dinv[row];
    float sl = dr * dr;                               // self-loop coefficient (fp32)

    const float2* xw2 = reinterpret_cast<const float2*>(g_xw4);
    float2 xv = reinterpret_cast<const float2*>(x)[(size_t)row * 32 + lane];
    float2 wv = xw2[(size_t)row * 32 + lane];
    float2 bv = reinterpret_cast<const float2*>(b)[lane];

    float h0 = xv.x + dr * z0 + sl * wv.x + bv.x;
    float h1 = xv.y + dr * z1 + sl * wv.y + bv.y;

    float s = h0 + h1;
    float sq = h0 * h0 + h1 * h1;
#pragma unroll
    for (int o = 16; o > 0; o >>= 1) {
        s  += __shfl_xor_sync(0xFFFFFFFF, s,  o);
        sq += __shfl_xor_sync(0xFFFFFFFF, sq, o);
    }
    float mu = s * (1.0f / D);
    float var = sq * (1.0f / D) - mu * mu;
    float rstd = rsqrtf(var + LN_EPS);

    float2 gv  = reinterpret_cast<const float2*>(gamma)[lane];
    float2 bev = reinterpret_cast<const float2*>(beta)[lane];

    float o0 = fmaxf((h0 - mu) * rstd * gv.x + bev.x, 0.f);
    float o1 = fmaxf((h1 - mu) * rstd * gv.y + bev.y, 0.f);

    reinterpret_cast<float2*>(out)[(size_t)row * 32 + lane] = make_float2(o0, o1);
}

// ---------------------------------------------------------------------------
extern "C" void kernel_launch(void* const* d_in, const int* in_sizes, int n_in,
                              void* d_out, int out_size) {
    const float* x = (const float*)d_in[0];
    const int* edge_index = (const int*)d_in[1];   // [2, E] int32
    const float* W = (const float*)d_in[2];
    const float* b = (const float*)d_in[3];
    const float* gamma = (const float*)d_in[4];
    const float* beta = (const float*)d_in[5];
    float* out = (float*)d_out;

    const int* src = edge_index;
    const int* dst = edge_index + N_EDGES;

    // K1: fused HMMA GEMM + edge binning (1 edge/thread, 1:8 interleave)
    fused_gemm_bin_kernel<<<TOTAL_BLOCKS, 256>>>(x, W, src, dst);
    // K2: dinv + y(fp16) + cnt snapshot + degi reset
    prep_scale_kernel<<<(N_NODES + 7) / 8, 256>>>();
    // K3: fused gather (fp16) + LN + ReLU
    gather_finalize_kernel<<<(N_NODES + 7) / 8, 256>>>(x, b, gamma, beta, out);
}

// round 17
// speedup vs baseline: 1.0336x; 1.0336x over previous
#include <cuda_runtime.h>
#include <cuda_fp16.h>
#include <stdint.h>

#define N_NODES 50000
#define N_EDGES 800000
#define D 64
#define LN_EPS 1e-5f
#define CAP 64                                    // deg mean 16, sigma 4; 64 = 12 sigma
#define ROWS_PER_BLK 128                          // 8 warps x 16 rows
#define GEMM_BLOCKS ((N_NODES + ROWS_PER_BLK - 1) / ROWS_PER_BLK)  // 391
#define BIN_T (N_EDGES / 8)                       // 100000 threads, 8 edges each
#define BIN_BLOCKS ((BIN_T + 255) / 256)          // 391  (== GEMM_BLOCKS)
#define TOTAL_BLOCKS (GEMM_BLOCKS + BIN_BLOCKS)   // 782
#define XH_STRIDE 72                              // halves; 144B rows, conflict-free

// Scratch (static device globals; zero-initialized at module load)
__device__ float4  g_xw4[N_NODES * (D / 4)];      // x @ W (fp32, self-loop path)
__device__ __half2 g_yh[N_NODES * (D / 2)];       // y = dinv * xw (fp16 gather table)
__device__ int   g_degi[N_NODES];                 // bin fill counters; zero between calls
__device__ int   g_cnt[N_NODES];                  // per-node edge count snapshot
__device__ float g_dinv[N_NODES];                 // rsqrt(1 + deg)
__device__ int   g_bin[N_NODES * CAP];            // src indices, bucketed by dst

__device__ __forceinline__ uint32_t smem_u32(const void* p) {
    return (uint32_t)__cvta_generic_to_shared(p);
}

// ---------------------------------------------------------------------------
// K1: fused  (a) xw = x @ W via HMMA (mma.sync m16n8k16, fp16 in, fp32 acc)
//            (b) edge binning, 8 edges/thread (2x int4 loads, MLP 8).
// blockIdx parity: even -> gemm, odd -> bin (391 each).
// ---------------------------------------------------------------------------
__global__ void fused_gemm_bin_kernel(const float* __restrict__ x,
                                      const float* __restrict__ W,
                                      const int* __restrict__ src,
                                      const int* __restrict__ dst) {
    int tid = threadIdx.x;          // 256 threads flat
    if (blockIdx.x & 1) {
        // -------- edge binning: 8 edges/thread --------
        int t = (blockIdx.x >> 1) * 256 + tid;
        if (t < BIN_T) {
            const int4* s4p = reinterpret_cast<const int4*>(src);
            const int4* d4p = reinterpret_cast<const int4*>(dst);
            int4 sA = __ldg(s4p + 2 * t), sB = __ldg(s4p + 2 * t + 1);
            int4 dA = __ldg(d4p + 2 * t), dB = __ldg(d4p + 2 * t + 1);
            int r;
            r = atomicAdd(&g_degi[dA.x], 1); if (r < CAP) g_bin[dA.x * CAP + r] = sA.x;
            r = atomicAdd(&g_degi[dA.y], 1); if (r < CAP) g_bin[dA.y * CAP + r] = sA.y;
            r = atomicAdd(&g_degi[dA.z], 1); if (r < CAP) g_bin[dA.z * CAP + r] = sA.z;
            r = atomicAdd(&g_degi[dA.w], 1); if (r < CAP) g_bin[dA.w * CAP + r] = sA.w;
            r = atomicAdd(&g_degi[dB.x], 1); if (r < CAP) g_bin[dB.x * CAP + r] = sB.x;
            r = atomicAdd(&g_degi[dB.y], 1); if (r < CAP) g_bin[dB.y * CAP + r] = sB.y;
            r = atomicAdd(&g_degi[dB.z], 1); if (r < CAP) g_bin[dB.z * CAP + r] = sB.z;
            r = atomicAdd(&g_degi[dB.w], 1); if (r < CAP) g_bin[dB.w * CAP + r] = sB.w;
        }
        return;
    }
    // -------- gemm: 128 rows/block, warp = 16 rows x 64 cols --------
    __shared__ __align__(16) __half Wh[D * XH_STRIDE];            // 9.2 KB  [k][n]
    __shared__ __align__(16) __half Xh[ROWS_PER_BLK * XH_STRIDE]; // 18.4 KB [r][k]

    int row0 = (blockIdx.x >> 1) * ROWS_PER_BLK;

    // stage W -> fp16 [k][n]
    {
        const float2* W2 = reinterpret_cast<const float2*>(W);
        for (int i = tid; i < D * (D / 2); i += 256) {
            int k = i >> 5, n2 = i & 31;
            float2 v = W2[i];
            *reinterpret_cast<__half2*>(&Wh[k * XH_STRIDE + n2 * 2]) =
                __floats2half2_rn(v.x, v.y);
        }
    }
    // stage x rows -> fp16 [r][k]
    {
        const float2* x2 = reinterpret_cast<const float2*>(x);
        for (int i = tid; i < ROWS_PER_BLK * (D / 2); i += 256) {
            int r = i >> 5, c2 = i & 31;
            int row = row0 + r;
            float2 v = (row < N_NODES) ? x2[(size_t)row * 32 + c2]
                                       : make_float2(0.f, 0.f);
            *reinterpret_cast<__half2*>(&Xh[r * XH_STRIDE + c2 * 2]) =
                __floats2half2_rn(v.x, v.y);
        }
    }
    __syncthreads();

    int warp = tid >> 5;
    int lane = tid & 31;
    int rw = warp * 16;                       // warp's first row within block

    float d0[8], d1[8], d2[8], d3[8];
#pragma unroll
    for (int nt = 0; nt < 8; nt++) { d0[nt] = d1[nt] = d2[nt] = d3[nt] = 0.f; }

    uint32_t a_base = smem_u32(Xh) +
        (uint32_t)(((rw + (lane & 15)) * XH_STRIDE + ((lane >> 4) << 3)) * 2);
    uint32_t b_base = smem_u32(Wh) + (uint32_t)(((lane & 15) * XH_STRIDE) * 2);

#pragma unroll
    for (int kc = 0; kc < 4; kc++) {          // k chunks of 16
        uint32_t a0, a1, a2, a3;
        asm volatile("ldmatrix.sync.aligned.m8n8.x4.shared.b16 {%0,%1,%2,%3}, [%4];"
                     : "=r"(a0), "=r"(a1), "=r"(a2), "=r"(a3)
                     : "r"(a_base + kc * 32));
#pragma unroll
        for (int nt = 0; nt < 8; nt++) {
            uint32_t b0, b1;
            asm volatile("ldmatrix.sync.aligned.m8n8.x2.trans.shared.b16 {%0,%1}, [%2];"
                         : "=r"(b0), "=r"(b1)
                         : "r"(b_base + (uint32_t)(kc * 16 * XH_STRIDE + nt * 8) * 2));
            asm volatile(
                "mma.sync.aligned.m16n8k16.row.col.f32.f16.f16.f32 "
                "{%0,%1,%2,%3}, {%4,%5,%6,%7}, {%8,%9}, {%0,%1,%2,%3};"
                : "+f"(d0[nt]), "+f"(d1[nt]), "+f"(d2[nt]), "+f"(d3[nt])
                : "r"(a0), "r"(a1), "r"(a2), "r"(a3), "r"(b0), "r"(b1));
        }
    }

    // write xw: lane g=l>>2 -> rows rw+g, rw+g+8; tg=l&3 -> col pair
    {
        int g = lane >> 2, tg = lane & 3;
        int rowA = row0 + rw + g;
        int rowB = rowA + 8;
        float2* xw2 = reinterpret_cast<float2*>(g_xw4);
#pragma unroll
        for (int nt = 0; nt < 8; nt++) {
            int cpair = nt * 4 + tg;
            if (rowA < N_NODES) xw2[(size_t)rowA * 32 + cpair] = make_float2(d0[nt], d1[nt]);
            if (rowB < N_NODES) xw2[(size_t)rowB * 32 + cpair] = make_float2(d2[nt], d3[nt]);
        }
    }
}

// ---------------------------------------------------------------------------
// K2: per node (warp per row): dinv = rsqrt(1+deg); y = half(dinv * xw);
// snapshot cnt; re-zero degi.
// ---------------------------------------------------------------------------
__global__ void prep_scale_kernel() {
    int warp = threadIdx.x >> 5;
    int lane = threadIdx.x & 31;
    int row = blockIdx.x * (blockDim.x >> 5) + warp;
    if (row >= N_NODES) return;

    int d = g_degi[row];
    float di = rsqrtf(1.0f + (float)d);
    if (lane == 0) {
        g_dinv[row] = di;
        g_cnt[row] = (d < CAP) ? d : CAP;
        g_degi[row] = 0;
    }
    const float2* xw2 = reinterpret_cast<const float2*>(g_xw4);
    float2 v = xw2[(size_t)row * 32 + lane];
    g_yh[(size_t)row * 32 + lane] = __floats2half2_rn(v.x * di, v.y * di);
}

// ---------------------------------------------------------------------------
// K3: fused gather + finalize. Warp per node. Indices loaded ONCE (lane-
// parallel, coalesced), then broadcast per-iteration via shfl -> no memory
// op in the index chain. Fallback __ldg for the ultra-rare deg>32.
// h = x + dinv_d * sum_s y_s + dinv_d^2 * xw_d + b ; LayerNorm; ReLU.
// ---------------------------------------------------------------------------
__global__ void gather_finalize_kernel(const float* __restrict__ x,
                                       const float* __restrict__ b,
                                       const float* __restrict__ gamma,
                                       const float* __restrict__ beta,
                                       float* __restrict__ out) {
    int warp = threadIdx.x >> 5;
    int lane = threadIdx.x & 31;
    int row = blockIdx.x * (blockDim.x >> 5) + warp;
    if (row >= N_NODES) return;

    int deg = g_cnt[row];
    const int* bin = g_bin + (size_t)row * CAP;

    // one coalesced 32-lane index load covers deg<=32 (all but ~2 nodes)
    int myidx = (lane < deg) ? __ldg(bin + lane) : 0;

    float z0 = 0.f, z1 = 0.f;
    int klim = (deg < 32) ? deg : 32;
#pragma unroll 4
    for (int k = 0; k < klim; k++) {
        int s = __shfl_sync(0xFFFFFFFF, myidx, k);   // no memory in chain
        float2 v = __half22float2(g_yh[(size_t)s * 32 + lane]);  // 128B/warp
        z0 += v.x;
        z1 += v.y;
    }
    for (int k = 32; k < deg; k++) {                 // ultra-rare tail
        int s = __ldg(bin + k);
        float2 v = __half22float2(g_yh[(size_t)s * 32 + lane]);
        z0 += v.x;
        z1 += v.y;
    }

    float dr = g_dinv[row];
    float sl = dr * dr;                               // self-loop coefficient (fp32)

    const float2* xw2 = reinterpret_cast<const float2*>(g_xw4);
    float2 xv = reinterpret_cast<const float2*>(x)[(size_t)row * 32 + lane];
    float2 wv = xw2[(size_t)row * 32 + lane];
    float2 bv = reinterpret_cast<const float2*>(b)[lane];

    float h0 = xv.x + dr * z0 + sl * wv.x + bv.x;
    float h1 = xv.y + dr * z1 + sl * wv.y + bv.y;

    float s = h0 + h1;
    float sq = h0 * h0 + h1 * h1;
#pragma unroll
    for (int o = 16; o > 0; o >>= 1) {
        s  += __shfl_xor_sync(0xFFFFFFFF, s,  o);
        sq += __shfl_xor_sync(0xFFFFFFFF, sq, o);
    }
    float mu = s * (1.0f / D);
    float var = sq * (1.0f / D) - mu * mu;
    float rstd = rsqrtf(var + LN_EPS);

    float2 gv  = reinterpret_cast<const float2*>(gamma)[lane];
    float2 bev = reinterpret_cast<const float2*>(beta)[lane];

    float o0 = fmaxf((h0 - mu) * rstd * gv.x + bev.x, 0.f);
    float o1 = fmaxf((h1 - mu) * rstd * gv.y + bev.y, 0.f);

    reinterpret_cast<float2*>(out)[(size_t)row * 32 + lane] = make_float2(o0, o1);
}

// ---------------------------------------------------------------------------
extern "C" void kernel_launch(void* const* d_in, const int* in_sizes, int n_in,
                              void* d_out, int out_size) {
    const float* x = (const float*)d_in[0];
    const int* edge_index = (const int*)d_in[1];   // [2, E] int32
    const float* W = (const float*)d_in[2];
    const float* b = (const float*)d_in[3];
    const float* gamma = (const float*)d_in[4];
    const float* beta = (const float*)d_in[5];
    float* out = (float*)d_out;

    const int* src = edge_index;
    const int* dst = edge_index + N_EDGES;

    // K1: fused HMMA GEMM + edge binning (8 edges/thread, 1:1 parity)
    fused_gemm_bin_kernel<<<TOTAL_BLOCKS, 256>>>(x, W, src, dst);
    // K2: dinv + y(fp16) + cnt snapshot + degi reset
    prep_scale_kernel<<<(N_NODES + 7) / 8, 256>>>();
    // K3: fused gather (shfl indices) + LN + ReLU
    gather_finalize_kernel<<<(N_NODES + 7) / 8, 256>>>(x, b, gamma, beta, out);
}